// round 1
// baseline (speedup 1.0000x reference)
#include <cuda_runtime.h>
#include <cuda_bf16.h>

// Problem constants
// B=4, T=1024, C=1024, H=16, D=64; M = B*T = 4096
// inputs: x[4,1024,1024], mask[1024,1024] (ignored; causal reproduced in-kernel),
//         W_in[1024,3072], b_in[3072], W_out[1024,1024], b_out[1024]
// output: [4,1024,1024] fp32

#define NB 4
#define NT 1024
#define NC 1024
#define NH 16
#define ND 64
#define NM (NB * NT)          // 4096

// Scratch in head layout [B,H,T,D] (16 MB each) + attention output [B,T,C]
__device__ float g_q[NB * NH * NT * ND];
__device__ float g_k[NB * NH * NT * ND];
__device__ float g_v[NB * NH * NT * ND];
__device__ float g_ao[NB * NT * NC];

// ---------------------------------------------------------------------------
// GEMM 1: qkv = x @ W_in + b_in, epilogue scatters into g_q/g_k/g_v [B,H,T,D]
// A: [4096,1024]  W: [1024,3072]
// Tile 64x64, BK=16, 256 threads, 4x4 per thread.
// ---------------------------------------------------------------------------
__global__ __launch_bounds__(256) void gemm_qkv(const float* __restrict__ A,
                                                const float* __restrict__ W,
                                                const float* __restrict__ bias) {
    __shared__ float As[16 * 65];   // [kk][row], padded
    __shared__ float Bs[16 * 64];   // [kk][col]
    const int tx = threadIdx.x, ty = threadIdx.y;
    const int tid = ty * 16 + tx;
    const int m0 = blockIdx.y * 64;
    const int n0 = blockIdx.x * 64;

    float acc[4][4] = {};

    const int ar = tid >> 4;      // 0..15 (A row within pass)
    const int ak = tid & 15;      // 0..15 (A k col)
    const int bc = tid & 63;      // 0..63 (B col)
    const int br = tid >> 6;      // 0..3  (B row within pass)

    for (int k0 = 0; k0 < NC; k0 += 16) {
        #pragma unroll
        for (int p = 0; p < 4; ++p) {
            int r = ar + p * 16;
            As[ak * 65 + r] = A[(m0 + r) * NC + k0 + ak];
        }
        #pragma unroll
        for (int p = 0; p < 4; ++p) {
            int rr = br + p * 4;
            Bs[rr * 64 + bc] = W[(k0 + rr) * 3072 + n0 + bc];
        }
        __syncthreads();
        #pragma unroll
        for (int kk = 0; kk < 16; ++kk) {
            float a[4], b[4];
            #pragma unroll
            for (int i = 0; i < 4; ++i) a[i] = As[kk * 65 + ty * 4 + i];
            #pragma unroll
            for (int j = 0; j < 4; ++j) b[j] = Bs[kk * 64 + tx * 4 + j];
            #pragma unroll
            for (int i = 0; i < 4; ++i)
                #pragma unroll
                for (int j = 0; j < 4; ++j)
                    acc[i][j] = fmaf(a[i], b[j], acc[i][j]);
        }
        __syncthreads();
    }

    // Epilogue: n0 tile is 64-wide, 1024 boundaries align -> whole tile same q/k/v
    const int which = n0 >> 10;
    float* dst = (which == 0) ? g_q : ((which == 1) ? g_k : g_v);
    #pragma unroll
    for (int i = 0; i < 4; ++i) {
        int m = m0 + ty * 4 + i;
        int bb = m >> 10;         // batch
        int t  = m & 1023;        // time
        #pragma unroll
        for (int j = 0; j < 4; ++j) {
            int n = n0 + tx * 4 + j;
            int c = n & 1023;
            int h = c >> 6;
            int d = c & 63;
            dst[(((bb * NH + h) * NT) + t) * ND + d] = acc[i][j] + bias[n];
        }
    }
}

// ---------------------------------------------------------------------------
// Flash attention (fp32, causal). One block = 64 queries of one (b,h).
// grid = (T/64, B*H), block 16x16. Smem: Qs/Ks/Vs each 64x65 fp32 (~48.8 KB dyn).
// Ks buffer is reused for P after softmax.
// ---------------------------------------------------------------------------
__global__ __launch_bounds__(256) void attn_kernel() {
    extern __shared__ float sm[];
    float* Qs = sm;                 // 64*65
    float* Ks = sm + 64 * 65;       // 64*65 (reused as P)
    float* Vs = sm + 2 * 64 * 65;   // 64*65

    const int tx = threadIdx.x, ty = threadIdx.y;
    const int tid = ty * 16 + tx;
    const int bh = blockIdx.y;      // 0..63
    const int qb = blockIdx.x;      // 0..15

    const int lr = tid >> 6;        // 0..3
    const int lc = tid & 63;        // 0..63

    const float* Qg = g_q + (bh * NT + qb * 64) * ND;
    #pragma unroll
    for (int p = 0; p < 16; ++p) {
        int r = p * 4 + lr;
        Qs[r * 65 + lc] = Qg[r * ND + lc];
    }

    float m_i[4], l_i[4], acc[4][4] = {};
    #pragma unroll
    for (int i = 0; i < 4; ++i) { m_i[i] = -1e30f; l_i[i] = 0.f; }

    for (int jb = 0; jb <= qb; ++jb) {
        const float* Kg = g_k + (bh * NT + jb * 64) * ND;
        const float* Vg = g_v + (bh * NT + jb * 64) * ND;

        __syncthreads();   // protect Ks(P)/Vs reads of previous iteration (and Qs store)
        #pragma unroll
        for (int p = 0; p < 16; ++p) {
            int r = p * 4 + lr;
            Ks[r * 65 + lc] = Kg[r * ND + lc];
            Vs[r * 65 + lc] = Vg[r * ND + lc];
        }
        __syncthreads();

        // S = Q @ K^T (4x4 per thread)
        float s[4][4] = {};
        #pragma unroll 8
        for (int kk = 0; kk < 64; ++kk) {
            float a[4], b[4];
            #pragma unroll
            for (int i = 0; i < 4; ++i) a[i] = Qs[(ty * 4 + i) * 65 + kk];
            #pragma unroll
            for (int j = 0; j < 4; ++j) b[j] = Ks[(tx * 4 + j) * 65 + kk];
            #pragma unroll
            for (int i = 0; i < 4; ++i)
                #pragma unroll
                for (int j = 0; j < 4; ++j)
                    s[i][j] = fmaf(a[i], b[j], s[i][j]);
        }

        // scale + causal mask (only diagonal block needs masking)
        #pragma unroll
        for (int i = 0; i < 4; ++i)
            #pragma unroll
            for (int j = 0; j < 4; ++j) {
                s[i][j] *= 0.125f;   // 1/sqrt(64)
                if (jb == qb && (tx * 4 + j) > (ty * 4 + i)) s[i][j] = -1e30f;
            }

        // online softmax update (row reduction over 16 tx lanes via shfl_xor)
        #pragma unroll
        for (int i = 0; i < 4; ++i) {
            float rmax = fmaxf(fmaxf(s[i][0], s[i][1]), fmaxf(s[i][2], s[i][3]));
            #pragma unroll
            for (int off = 8; off; off >>= 1)
                rmax = fmaxf(rmax, __shfl_xor_sync(0xffffffffu, rmax, off));
            float mnew = fmaxf(m_i[i], rmax);
            float rsum = 0.f;
            #pragma unroll
            for (int j = 0; j < 4; ++j) {
                s[i][j] = __expf(s[i][j] - mnew);
                rsum += s[i][j];
            }
            #pragma unroll
            for (int off = 8; off; off >>= 1)
                rsum += __shfl_xor_sync(0xffffffffu, rsum, off);
            float sc = __expf(m_i[i] - mnew);
            l_i[i] = l_i[i] * sc + rsum;
            m_i[i] = mnew;
            #pragma unroll
            for (int j = 0; j < 4; ++j) acc[i][j] *= sc;
        }

        __syncthreads();   // everyone done reading Ks as K
        // write P into Ks buffer
        #pragma unroll
        for (int i = 0; i < 4; ++i)
            #pragma unroll
            for (int j = 0; j < 4; ++j)
                Ks[(ty * 4 + i) * 65 + tx * 4 + j] = s[i][j];
        __syncthreads();

        // O += P @ V
        #pragma unroll 8
        for (int kk = 0; kk < 64; ++kk) {
            float pa[4], vb[4];
            #pragma unroll
            for (int i = 0; i < 4; ++i) pa[i] = Ks[(ty * 4 + i) * 65 + kk];
            #pragma unroll
            for (int j = 0; j < 4; ++j) vb[j] = Vs[kk * 65 + tx * 4 + j];
            #pragma unroll
            for (int i = 0; i < 4; ++i)
                #pragma unroll
                for (int j = 0; j < 4; ++j)
                    acc[i][j] = fmaf(pa[i], vb[j], acc[i][j]);
        }
    }

    // epilogue: write [B,T,C] layout
    const int b = bh >> 4;
    const int h = bh & 15;
    #pragma unroll
    for (int i = 0; i < 4; ++i) {
        float inv = 1.f / l_i[i];
        int t = qb * 64 + ty * 4 + i;
        #pragma unroll
        for (int j = 0; j < 4; ++j) {
            g_ao[(b * NT + t) * NC + h * 64 + tx * 4 + j] = acc[i][j] * inv;
        }
    }
}

// ---------------------------------------------------------------------------
// GEMM 3: out = g_ao @ W_out + b_out
// ---------------------------------------------------------------------------
__global__ __launch_bounds__(256) void gemm_out(const float* __restrict__ W,
                                                const float* __restrict__ bias,
                                                float* __restrict__ out) {
    __shared__ float As[16 * 65];
    __shared__ float Bs[16 * 64];
    const int tx = threadIdx.x, ty = threadIdx.y;
    const int tid = ty * 16 + tx;
    const int m0 = blockIdx.y * 64;
    const int n0 = blockIdx.x * 64;

    float acc[4][4] = {};

    const int ar = tid >> 4;
    const int ak = tid & 15;
    const int bc = tid & 63;
    const int br = tid >> 6;

    for (int k0 = 0; k0 < NC; k0 += 16) {
        #pragma unroll
        for (int p = 0; p < 4; ++p) {
            int r = ar + p * 16;
            As[ak * 65 + r] = g_ao[(m0 + r) * NC + k0 + ak];
        }
        #pragma unroll
        for (int p = 0; p < 4; ++p) {
            int rr = br + p * 4;
            Bs[rr * 64 + bc] = W[(k0 + rr) * NC + n0 + bc];
        }
        __syncthreads();
        #pragma unroll
        for (int kk = 0; kk < 16; ++kk) {
            float a[4], b[4];
            #pragma unroll
            for (int i = 0; i < 4; ++i) a[i] = As[kk * 65 + ty * 4 + i];
            #pragma unroll
            for (int j = 0; j < 4; ++j) b[j] = Bs[kk * 64 + tx * 4 + j];
            #pragma unroll
            for (int i = 0; i < 4; ++i)
                #pragma unroll
                for (int j = 0; j < 4; ++j)
                    acc[i][j] = fmaf(a[i], b[j], acc[i][j]);
        }
        __syncthreads();
    }

    #pragma unroll
    for (int i = 0; i < 4; ++i) {
        int m = m0 + ty * 4 + i;
        #pragma unroll
        for (int j = 0; j < 4; ++j) {
            int n = n0 + tx * 4 + j;
            out[m * NC + n] = acc[i][j] + bias[n];
        }
    }
}

extern "C" void kernel_launch(void* const* d_in, const int* in_sizes, int n_in,
                              void* d_out, int out_size) {
    const float* x     = (const float*)d_in[0];
    // d_in[1] = mask  (causal -1e9 mask; reproduced exactly in-kernel, unused)
    const float* W_in  = (const float*)d_in[2];
    const float* b_in  = (const float*)d_in[3];
    const float* W_out = (const float*)d_in[4];
    const float* b_out = (const float*)d_in[5];
    float* out = (float*)d_out;

    dim3 blk(16, 16);

    // QKV projection: M=4096, N=3072
    gemm_qkv<<<dim3(48, 64), blk>>>(x, W_in, b_in);

    // Flash attention
    const int attn_smem = 3 * 64 * 65 * (int)sizeof(float);  // 49920 B
    cudaFuncSetAttribute(attn_kernel, cudaFuncAttributeMaxDynamicSharedMemorySize, attn_smem);
    attn_kernel<<<dim3(16, 64), blk, attn_smem>>>();

    // Output projection: M=4096, N=1024
    gemm_out<<<dim3(16, 64), blk>>>(W_out, b_out, out);
}

// round 4
// speedup vs baseline: 2.0053x; 2.0053x over previous
#include <cuda_runtime.h>
#include <cstdint>

// Problem: B=4, T=1024, C=1024, H=16, D=64; M = B*T = 4096
// inputs: x[4,1024,1024], mask (ignored; exact causal mask reproduced in-kernel),
//         W_in[1024,3072], b_in[3072], W_out[1024,1024], b_out[1024]
// output: [4,1024,1024] fp32

#define NBATCH 4
#define NTIME 1024
#define NCH   1024
#define NHEAD 16
#define NDIM  64

// ---------------------------------------------------------------------------
// Device scratch, 64 MB total (matches R1's known-good footprint) with
// lifetime overlays:
//   g_qkv  [48MB]: q|k|v head-layout tensors. The first 4MB (Q region) is
//                  reused for W_out^T AFTER attention (Q dead by then).
//   g_shr  [16MB]: W_in^T (12MB, dead after gemm_qkv) then g_ao (16MB).
// ---------------------------------------------------------------------------
__device__ float g_qkv[3 * NBATCH * NHEAD * NTIME * NDIM];  // 48 MB
__device__ float g_shr[NBATCH * NTIME * NCH];               // 16 MB

#define QKV_SZ (NBATCH * NHEAD * NTIME * NDIM)   // 4M floats

// ===========================================================================
// PTX helpers (base sm_100 target — NO 'a'-suffix features)
// ===========================================================================
__device__ __forceinline__ uint32_t smem_u32(const void* p) {
    uint32_t a;
    asm("{ .reg .u64 t; cvta.to.shared.u64 t, %1; cvt.u32.u64 %0, t; }" : "=r"(a) : "l"(p));
    return a;
}

__device__ __forceinline__ void cp_async16(uint32_t dst, const void* src) {
    asm volatile("cp.async.cg.shared.global [%0], [%1], 16;" :: "r"(dst), "l"(src));
}
#define CP_COMMIT() asm volatile("cp.async.commit_group;" ::: "memory")
#define CP_WAIT(n)  asm volatile("cp.async.wait_group %0;" :: "n"(n) : "memory")

__device__ __forceinline__ uint32_t f2tf(float f) {
    uint32_t r;
    asm("cvt.rna.tf32.f32 %0, %1;" : "=r"(r) : "f"(f));
    return r;
}

__device__ __forceinline__ float lds_f(uint32_t a) {
    float v;
    asm volatile("ld.shared.f32 %0, [%1];" : "=f"(v) : "r"(a));
    return v;
}

__device__ __forceinline__ void mma_tf32(float* d, const uint32_t* a, const uint32_t* b) {
    asm volatile(
        "mma.sync.aligned.m16n8k8.row.col.f32.tf32.tf32.f32 "
        "{%0,%1,%2,%3}, {%4,%5,%6,%7}, {%8,%9}, {%0,%1,%2,%3};"
        : "+f"(d[0]), "+f"(d[1]), "+f"(d[2]), "+f"(d[3])
        : "r"(a[0]), "r"(a[1]), "r"(a[2]), "r"(a[3]), "r"(b[0]), "r"(b[1]));
}

// ===========================================================================
// tf32 mma.sync GEMM: D[M x N] = A[M x K] @ Bt[N x K]^T (+bias)
// CTA tile 128x128, BK=32, 3-stage cp.async pipeline, 8 warps (4m x 2n),
// warp tile 32x64. XOR-swizzled smem -> conflict-free LDS fragment loads.
// mode 0: out[m*1024+n] = acc + bias[n]
// mode 1: scatter into q/k/v head layout [B,H,T,D] + bias
// ===========================================================================
#define BM 128
#define BN 128
#define BK 32
#define STAGES 3
#define TILE_BYTES (BM * BK * 4)          // 16384
#define STAGE_BYTES (2 * TILE_BYTES)      // 32768 (A then B)
#define GEMM_SMEM (STAGES * STAGE_BYTES)  // 98304

// swizzled smem byte address for element (row, k)
__device__ __forceinline__ uint32_t sw_addr(uint32_t base, int row, int k) {
    return base + row * 128 + ((((k >> 2) ^ row) & 7) << 4) + ((k & 3) << 2);
}

__global__ __launch_bounds__(256, 1) void gemm_mma(
    const float* __restrict__ A,    // [M,K] row-major
    const float* __restrict__ Bt,   // [N,K] row-major (K-major B)
    const float* __restrict__ bias,
    float* __restrict__ outp,
    int K, int mode)
{
    extern __shared__ char smem[];
    const uint32_t base = smem_u32(smem);
    const int tid = threadIdx.x;
    const int lane = tid & 31, wid = tid >> 5;
    const int wm = wid >> 1, wn = wid & 1;   // 4 x 2 warp grid
    const int m0 = blockIdx.y * BM;
    const int n0 = blockIdx.x * BN;
    const int NK = K / BK;

    // ---- stage loader: each thread moves 4 x 16B per tile ----
    auto load_stage = [&](int kt, int s) {
        const uint32_t sA = base + s * STAGE_BYTES;
        const uint32_t sB = sA + TILE_BYTES;
        const int k0 = kt * BK;
        #pragma unroll
        for (int i = 0; i < 4; ++i) {
            int chunk = tid + i * 256;
            int row = chunk >> 3, c16 = chunk & 7;
            uint32_t off = row * 128 + (((c16 ^ row) & 7) << 4);
            cp_async16(sA + off, A  + (size_t)(m0 + row) * K + k0 + c16 * 4);
            cp_async16(sB + off, Bt + (size_t)(n0 + row) * K + k0 + c16 * 4);
        }
    };

    float acc[2][8][4] = {};

    #pragma unroll
    for (int s = 0; s < STAGES - 1; ++s) { load_stage(s, s); CP_COMMIT(); }

    for (int kt = 0; kt < NK; ++kt) {
        CP_WAIT(STAGES - 2);
        __syncthreads();

        int ktn = kt + STAGES - 1;
        if (ktn < NK) load_stage(ktn, ktn % STAGES);
        CP_COMMIT();

        const int s = kt % STAGES;
        const uint32_t sA = base + s * STAGE_BYTES;
        const uint32_t sB = sA + TILE_BYTES;

        #pragma unroll
        for (int ks = 0; ks < 4; ++ks) {
            const int kk = ks * 8;
            uint32_t af[2][4], bf[8][2];
            #pragma unroll
            for (int mt = 0; mt < 2; ++mt) {
                int r = wm * 32 + mt * 16 + (lane >> 2);
                int c = kk + (lane & 3);
                af[mt][0] = f2tf(lds_f(sw_addr(sA, r,     c)));
                af[mt][1] = f2tf(lds_f(sw_addr(sA, r + 8, c)));
                af[mt][2] = f2tf(lds_f(sw_addr(sA, r,     c + 4)));
                af[mt][3] = f2tf(lds_f(sw_addr(sA, r + 8, c + 4)));
            }
            #pragma unroll
            for (int nt = 0; nt < 8; ++nt) {
                int n = wn * 64 + nt * 8 + (lane >> 2);
                int c = kk + (lane & 3);
                bf[nt][0] = f2tf(lds_f(sw_addr(sB, n, c)));
                bf[nt][1] = f2tf(lds_f(sw_addr(sB, n, c + 4)));
            }
            #pragma unroll
            for (int mt = 0; mt < 2; ++mt)
                #pragma unroll
                for (int nt = 0; nt < 8; ++nt)
                    mma_tf32(acc[mt][nt], af[mt], bf[nt]);
        }
    }

    // ---- epilogue ----
    #pragma unroll
    for (int mt = 0; mt < 2; ++mt) {
        const int r0 = m0 + wm * 32 + mt * 16 + (lane >> 2);
        #pragma unroll
        for (int nt = 0; nt < 8; ++nt) {
            const int c = n0 + wn * 64 + nt * 8 + (lane & 3) * 2;
            const float bx = __ldg(bias + c), by = __ldg(bias + c + 1);
            if (mode == 0) {
                float2 v0 = make_float2(acc[mt][nt][0] + bx, acc[mt][nt][1] + by);
                float2 v1 = make_float2(acc[mt][nt][2] + bx, acc[mt][nt][3] + by);
                *reinterpret_cast<float2*>(outp + (size_t)r0 * NCH + c) = v0;
                *reinterpret_cast<float2*>(outp + (size_t)(r0 + 8) * NCH + c) = v1;
            } else {
                const int which = n0 >> 10;
                float* dst = g_qkv + (size_t)which * QKV_SZ;
                const int cc = c & 1023;
                const int h = cc >> 6, d = cc & 63;
                {
                    int bb = r0 >> 10, t = r0 & 1023;
                    float2 v = make_float2(acc[mt][nt][0] + bx, acc[mt][nt][1] + by);
                    *reinterpret_cast<float2*>(dst + ((size_t)((bb * NHEAD + h) * NTIME) + t) * NDIM + d) = v;
                }
                {
                    int r1 = r0 + 8;
                    int bb = r1 >> 10, t = r1 & 1023;
                    float2 v = make_float2(acc[mt][nt][2] + bx, acc[mt][nt][3] + by);
                    *reinterpret_cast<float2*>(dst + ((size_t)((bb * NHEAD + h) * NTIME) + t) * NDIM + d) = v;
                }
            }
        }
    }
}

// ===========================================================================
// 32x32 tiled transpose: src[R][C] -> dst[C][R]
// ===========================================================================
__global__ __launch_bounds__(256) void transpose_k(const float* __restrict__ src,
                                                   float* __restrict__ dst,
                                                   int R, int C) {
    __shared__ float t[32][33];
    const int bx = blockIdx.x * 32, by = blockIdx.y * 32;
    const int tx = threadIdx.x, ty = threadIdx.y;
    #pragma unroll
    for (int i = 0; i < 32; i += 8)
        t[ty + i][tx] = src[(size_t)(by + ty + i) * C + bx + tx];
    __syncthreads();
    #pragma unroll
    for (int i = 0; i < 32; i += 8)
        dst[(size_t)(bx + ty + i) * R + by + tx] = t[tx][ty + i];
}

// ===========================================================================
// Flash attention (fp32, causal) — reads g_qkv, writes g_shr (as g_ao)
// ===========================================================================
__global__ __launch_bounds__(256) void attn_kernel() {
    extern __shared__ float sm[];
    float* Qs = sm;
    float* Ks = sm + 64 * 65;
    float* Vs = sm + 2 * 64 * 65;

    const int tx = threadIdx.x, ty = threadIdx.y;
    const int tid = ty * 16 + tx;
    const int bh = blockIdx.y;
    const int qb = blockIdx.x;

    const int lr = tid >> 6;
    const int lc = tid & 63;

    const float* gq = g_qkv;
    const float* gk = g_qkv + QKV_SZ;
    const float* gv = g_qkv + 2 * (size_t)QKV_SZ;

    const float* Qg = gq + (size_t)(bh * NTIME + qb * 64) * NDIM;
    #pragma unroll
    for (int p = 0; p < 16; ++p) {
        int r = p * 4 + lr;
        Qs[r * 65 + lc] = Qg[r * NDIM + lc];
    }

    float m_i[4], l_i[4], acc[4][4] = {};
    #pragma unroll
    for (int i = 0; i < 4; ++i) { m_i[i] = -1e30f; l_i[i] = 0.f; }

    for (int jb = 0; jb <= qb; ++jb) {
        const float* Kg = gk + (size_t)(bh * NTIME + jb * 64) * NDIM;
        const float* Vg = gv + (size_t)(bh * NTIME + jb * 64) * NDIM;

        __syncthreads();
        #pragma unroll
        for (int p = 0; p < 16; ++p) {
            int r = p * 4 + lr;
            Ks[r * 65 + lc] = Kg[r * NDIM + lc];
            Vs[r * 65 + lc] = Vg[r * NDIM + lc];
        }
        __syncthreads();

        float s[4][4] = {};
        #pragma unroll 8
        for (int kk = 0; kk < 64; ++kk) {
            float a[4], b[4];
            #pragma unroll
            for (int i = 0; i < 4; ++i) a[i] = Qs[(ty * 4 + i) * 65 + kk];
            #pragma unroll
            for (int j = 0; j < 4; ++j) b[j] = Ks[(tx * 4 + j) * 65 + kk];
            #pragma unroll
            for (int i = 0; i < 4; ++i)
                #pragma unroll
                for (int j = 0; j < 4; ++j)
                    s[i][j] = fmaf(a[i], b[j], s[i][j]);
        }

        #pragma unroll
        for (int i = 0; i < 4; ++i)
            #pragma unroll
            for (int j = 0; j < 4; ++j) {
                s[i][j] *= 0.125f;
                if (jb == qb && (tx * 4 + j) > (ty * 4 + i)) s[i][j] = -1e30f;
            }

        #pragma unroll
        for (int i = 0; i < 4; ++i) {
            float rmax = fmaxf(fmaxf(s[i][0], s[i][1]), fmaxf(s[i][2], s[i][3]));
            #pragma unroll
            for (int off = 8; off; off >>= 1)
                rmax = fmaxf(rmax, __shfl_xor_sync(0xffffffffu, rmax, off));
            float mnew = fmaxf(m_i[i], rmax);
            float rsum = 0.f;
            #pragma unroll
            for (int j = 0; j < 4; ++j) {
                s[i][j] = __expf(s[i][j] - mnew);
                rsum += s[i][j];
            }
            #pragma unroll
            for (int off = 8; off; off >>= 1)
                rsum += __shfl_xor_sync(0xffffffffu, rsum, off);
            float sc = __expf(m_i[i] - mnew);
            l_i[i] = l_i[i] * sc + rsum;
            m_i[i] = mnew;
            #pragma unroll
            for (int j = 0; j < 4; ++j) acc[i][j] *= sc;
        }

        __syncthreads();
        #pragma unroll
        for (int i = 0; i < 4; ++i)
            #pragma unroll
            for (int j = 0; j < 4; ++j)
                Ks[(ty * 4 + i) * 65 + tx * 4 + j] = s[i][j];
        __syncthreads();

        #pragma unroll 8
        for (int kk = 0; kk < 64; ++kk) {
            float pa[4], vb[4];
            #pragma unroll
            for (int i = 0; i < 4; ++i) pa[i] = Ks[(ty * 4 + i) * 65 + kk];
            #pragma unroll
            for (int j = 0; j < 4; ++j) vb[j] = Vs[kk * 65 + tx * 4 + j];
            #pragma unroll
            for (int i = 0; i < 4; ++i)
                #pragma unroll
                for (int j = 0; j < 4; ++j)
                    acc[i][j] = fmaf(pa[i], vb[j], acc[i][j]);
        }
    }

    const int b = bh >> 4;
    const int h = bh & 15;
    #pragma unroll
    for (int i = 0; i < 4; ++i) {
        float inv = 1.f / l_i[i];
        int t = qb * 64 + ty * 4 + i;
        #pragma unroll
        for (int j = 0; j < 4; ++j) {
            g_shr[(size_t)(b * NTIME + t) * NCH + h * 64 + tx * 4 + j] = acc[i][j] * inv;
        }
    }
}

// ===========================================================================
// Host launch
// ===========================================================================
extern "C" void kernel_launch(void* const* d_in, const int* in_sizes, int n_in,
                              void* d_out, int out_size) {
    const float* x     = (const float*)d_in[0];
    // d_in[1] = mask (exact causal -1e9 mask; reproduced in-kernel, unused)
    const float* W_in  = (const float*)d_in[2];
    const float* b_in  = (const float*)d_in[3];
    const float* W_out = (const float*)d_in[4];
    const float* b_out = (const float*)d_in[5];
    float* out = (float*)d_out;

    void *p_qkv = nullptr, *p_shr = nullptr;
    cudaGetSymbolAddress(&p_qkv, g_qkv);
    cudaGetSymbolAddress(&p_shr, g_shr);
    float* qkv = (float*)p_qkv;     // q | k | v  (Q region reused for W_out^T later)
    float* shr = (float*)p_shr;     // W_in^T then g_ao

    cudaFuncSetAttribute(gemm_mma, cudaFuncAttributeMaxDynamicSharedMemorySize, GEMM_SMEM);

    // 1) W_in^T into shared region (12 MB of 16 MB)
    transpose_k<<<dim3(96, 32), dim3(32, 8)>>>(W_in, shr, 1024, 3072);

    // 2) QKV projection: M=4096, N=3072, K=1024 (mode 1: scatter to head layout)
    gemm_mma<<<dim3(24, 32), 256, GEMM_SMEM>>>(x, shr, b_in, nullptr, 1024, 1);

    // 3) Flash attention: reads qkv, writes attention output into shr (W_in^T dead)
    const int attn_smem = 3 * 64 * 65 * (int)sizeof(float);
    cudaFuncSetAttribute(attn_kernel, cudaFuncAttributeMaxDynamicSharedMemorySize, attn_smem);
    attn_kernel<<<dim3(16, 64), dim3(16, 16), attn_smem>>>();

    // 4) W_out^T into Q region of qkv (Q dead after attention)
    transpose_k<<<dim3(32, 32), dim3(32, 8)>>>(W_out, qkv, 1024, 1024);

    // 5) Output projection: M=4096, N=1024, K=1024 (mode 0: direct write + bias)
    gemm_mma<<<dim3(8, 32), 256, GEMM_SMEM>>>(shr, qkv, b_out, out, 1024, 0);
}

// round 5
// speedup vs baseline: 3.1528x; 1.5722x over previous
#include <cuda_runtime.h>
#include <cstdint>

// Problem: B=4, T=1024, C=1024, H=16, D=64; M = B*T = 4096
// inputs: x[4,1024,1024], mask (ignored; exact causal mask reproduced in-kernel),
//         W_in[1024,3072], b_in[3072], W_out[1024,1024], b_out[1024]
// output: [4,1024,1024] fp32

#define NBATCH 4
#define NTIME 1024
#define NCH   1024
#define NHEAD 16
#define NDIM  64

// 64 MB scratch with lifetime overlays (known-good footprint):
//   g_qkv [48MB]: q|k|v head layout; Q region reused for W_out^T after attention.
//   g_shr [16MB]: W_in^T (dead after gemm_qkv), then attention output [B,T,C].
__device__ float g_qkv[3 * NBATCH * NHEAD * NTIME * NDIM];  // 48 MB
__device__ float g_shr[NBATCH * NTIME * NCH];               // 16 MB

#define QKV_SZ (NBATCH * NHEAD * NTIME * NDIM)   // 4M floats

// ===========================================================================
// PTX helpers (base sm_100 target — NO 'a'-suffix features)
// ===========================================================================
__device__ __forceinline__ uint32_t smem_u32(const void* p) {
    uint32_t a;
    asm("{ .reg .u64 t; cvta.to.shared.u64 t, %1; cvt.u32.u64 %0, t; }" : "=r"(a) : "l"(p));
    return a;
}

__device__ __forceinline__ void cp_async16(uint32_t dst, const void* src) {
    asm volatile("cp.async.cg.shared.global [%0], [%1], 16;" :: "r"(dst), "l"(src));
}
#define CP_COMMIT() asm volatile("cp.async.commit_group;" ::: "memory")
#define CP_WAIT(n)  asm volatile("cp.async.wait_group %0;" :: "n"(n) : "memory")

__device__ __forceinline__ uint32_t f2tf(float f) {
    uint32_t r;
    asm("cvt.rna.tf32.f32 %0, %1;" : "=r"(r) : "f"(f));
    return r;
}

__device__ __forceinline__ float lds_f(uint32_t a) {
    float v;
    asm volatile("ld.shared.f32 %0, [%1];" : "=f"(v) : "r"(a));
    return v;
}
__device__ __forceinline__ uint32_t lds_u(uint32_t a) {
    uint32_t v;
    asm volatile("ld.shared.b32 %0, [%1];" : "=r"(v) : "r"(a));
    return v;
}
__device__ __forceinline__ void sts_v2u(uint32_t a, uint32_t x, uint32_t y) {
    asm volatile("st.shared.v2.b32 [%0], {%1, %2};" :: "r"(a), "r"(x), "r"(y) : "memory");
}

__device__ __forceinline__ void mma_tf32(float* d, const uint32_t* a, const uint32_t* b) {
    asm volatile(
        "mma.sync.aligned.m16n8k8.row.col.f32.tf32.tf32.f32 "
        "{%0,%1,%2,%3}, {%4,%5,%6,%7}, {%8,%9}, {%0,%1,%2,%3};"
        : "+f"(d[0]), "+f"(d[1]), "+f"(d[2]), "+f"(d[3])
        : "r"(a[0]), "r"(a[1]), "r"(a[2]), "r"(a[3]), "r"(b[0]), "r"(b[1]));
}

// Polynomial exp2 on FMA/ALU pipes (avoids MUFU throughput wall).
// x <= 0 expected; clamps below -126. Rel err ~2e-6 on [-0.5,0.5] frac.
__device__ __forceinline__ float exp2p(float x) {
    x = fmaxf(x, -126.0f);
    float n = rintf(x);
    float f = x - n;
    float p = 0.0013333558f;
    p = fmaf(p, f, 0.0096181291f);
    p = fmaf(p, f, 0.0555041087f);
    p = fmaf(p, f, 0.2402265070f);
    p = fmaf(p, f, 0.6931471806f);
    p = fmaf(p, f, 1.0f);
    int e = (int)n;
    return __int_as_float((e + 127) << 23) * p;
}

// ===========================================================================
// tf32 mma.sync GEMM (unchanged from R4): D = A @ Bt^T (+bias)
// ===========================================================================
#define BM 128
#define BN 128
#define BK 32
#define STAGES 3
#define TILE_BYTES (BM * BK * 4)
#define STAGE_BYTES (2 * TILE_BYTES)
#define GEMM_SMEM (STAGES * STAGE_BYTES)

__device__ __forceinline__ uint32_t sw_addr(uint32_t base, int row, int k) {
    return base + row * 128 + ((((k >> 2) ^ row) & 7) << 4) + ((k & 3) << 2);
}

__global__ __launch_bounds__(256, 1) void gemm_mma(
    const float* __restrict__ A, const float* __restrict__ Bt,
    const float* __restrict__ bias, float* __restrict__ outp, int K, int mode)
{
    extern __shared__ char smem[];
    const uint32_t base = smem_u32(smem);
    const int tid = threadIdx.x;
    const int lane = tid & 31, wid = tid >> 5;
    const int wm = wid >> 1, wn = wid & 1;
    const int m0 = blockIdx.y * BM;
    const int n0 = blockIdx.x * BN;
    const int NK = K / BK;

    auto load_stage = [&](int kt, int s) {
        const uint32_t sA = base + s * STAGE_BYTES;
        const uint32_t sB = sA + TILE_BYTES;
        const int k0 = kt * BK;
        #pragma unroll
        for (int i = 0; i < 4; ++i) {
            int chunk = tid + i * 256;
            int row = chunk >> 3, c16 = chunk & 7;
            uint32_t off = row * 128 + (((c16 ^ row) & 7) << 4);
            cp_async16(sA + off, A  + (size_t)(m0 + row) * K + k0 + c16 * 4);
            cp_async16(sB + off, Bt + (size_t)(n0 + row) * K + k0 + c16 * 4);
        }
    };

    float acc[2][8][4] = {};

    #pragma unroll
    for (int s = 0; s < STAGES - 1; ++s) { load_stage(s, s); CP_COMMIT(); }

    for (int kt = 0; kt < NK; ++kt) {
        CP_WAIT(STAGES - 2);
        __syncthreads();

        int ktn = kt + STAGES - 1;
        if (ktn < NK) load_stage(ktn, ktn % STAGES);
        CP_COMMIT();

        const int s = kt % STAGES;
        const uint32_t sA = base + s * STAGE_BYTES;
        const uint32_t sB = sA + TILE_BYTES;

        #pragma unroll
        for (int ks = 0; ks < 4; ++ks) {
            const int kk = ks * 8;
            uint32_t af[2][4], bf[8][2];
            #pragma unroll
            for (int mt = 0; mt < 2; ++mt) {
                int r = wm * 32 + mt * 16 + (lane >> 2);
                int c = kk + (lane & 3);
                af[mt][0] = f2tf(lds_f(sw_addr(sA, r,     c)));
                af[mt][1] = f2tf(lds_f(sw_addr(sA, r + 8, c)));
                af[mt][2] = f2tf(lds_f(sw_addr(sA, r,     c + 4)));
                af[mt][3] = f2tf(lds_f(sw_addr(sA, r + 8, c + 4)));
            }
            #pragma unroll
            for (int nt = 0; nt < 8; ++nt) {
                int n = wn * 64 + nt * 8 + (lane >> 2);
                int c = kk + (lane & 3);
                bf[nt][0] = f2tf(lds_f(sw_addr(sB, n, c)));
                bf[nt][1] = f2tf(lds_f(sw_addr(sB, n, c + 4)));
            }
            #pragma unroll
            for (int mt = 0; mt < 2; ++mt)
                #pragma unroll
                for (int nt = 0; nt < 8; ++nt)
                    mma_tf32(acc[mt][nt], af[mt], bf[nt]);
        }
    }

    #pragma unroll
    for (int mt = 0; mt < 2; ++mt) {
        const int r0 = m0 + wm * 32 + mt * 16 + (lane >> 2);
        #pragma unroll
        for (int nt = 0; nt < 8; ++nt) {
            const int c = n0 + wn * 64 + nt * 8 + (lane & 3) * 2;
            const float bx = __ldg(bias + c), by = __ldg(bias + c + 1);
            if (mode == 0) {
                float2 v0 = make_float2(acc[mt][nt][0] + bx, acc[mt][nt][1] + by);
                float2 v1 = make_float2(acc[mt][nt][2] + bx, acc[mt][nt][3] + by);
                *reinterpret_cast<float2*>(outp + (size_t)r0 * NCH + c) = v0;
                *reinterpret_cast<float2*>(outp + (size_t)(r0 + 8) * NCH + c) = v1;
            } else {
                const int which = n0 >> 10;
                float* dst = g_qkv + (size_t)which * QKV_SZ;
                const int cc = c & 1023;
                const int h = cc >> 6, d = cc & 63;
                {
                    int bb = r0 >> 10, t = r0 & 1023;
                    float2 v = make_float2(acc[mt][nt][0] + bx, acc[mt][nt][1] + by);
                    *reinterpret_cast<float2*>(dst + ((size_t)((bb * NHEAD + h) * NTIME) + t) * NDIM + d) = v;
                }
                {
                    int r1 = r0 + 8;
                    int bb = r1 >> 10, t = r1 & 1023;
                    float2 v = make_float2(acc[mt][nt][2] + bx, acc[mt][nt][3] + by);
                    *reinterpret_cast<float2*>(dst + ((size_t)((bb * NHEAD + h) * NTIME) + t) * NDIM + d) = v;
                }
            }
        }
    }
}

// ===========================================================================
// 32x32 tiled transpose
// ===========================================================================
__global__ __launch_bounds__(256) void transpose_k(const float* __restrict__ src,
                                                   float* __restrict__ dst,
                                                   int R, int C) {
    __shared__ float t[32][33];
    const int bx = blockIdx.x * 32, by = blockIdx.y * 32;
    const int tx = threadIdx.x, ty = threadIdx.y;
    #pragma unroll
    for (int i = 0; i < 32; i += 8)
        t[ty + i][tx] = src[(size_t)(by + ty + i) * C + bx + tx];
    __syncthreads();
    #pragma unroll
    for (int i = 0; i < 32; i += 8)
        dst[(size_t)(bx + ty + i) * R + by + tx] = t[tx][ty + i];
}

// ===========================================================================
// Tensor-core flash attention (tf32 mma, poly-exp2 softmax, causal).
// CTA = 64 queries of one (b,h); 4 warps x 16 rows; 64-key blocks,
// double-buffered cp.async K/V. Q fragments register-resident; P reuses the
// Q smem buffer (per-warp-private rows). Strides: Q/K/P 68 floats (bank map
// 4*row+col, conflict-free), V 72 floats (8*row+col, conflict-free).
// ===========================================================================
#define QS_STRIDE_B 272                     // 68 floats
#define VS_STRIDE_B 288                     // 72 floats
#define KS_OFF 17408                        // after Qs (64*272)
#define VS_OFF (KS_OFF + 2 * 17408)         // 52224
#define ATT_SMEM (VS_OFF + 2 * 18432)       // 89088

__global__ __launch_bounds__(128, 2) void attn_mma(float* __restrict__ gout) {
    extern __shared__ char smc[];
    const uint32_t base = smem_u32(smc);
    const int tid = threadIdx.x, lane = tid & 31, wid = tid >> 5;
    const int grp = lane >> 2, qd = lane & 3;
    const int qi = blockIdx.x;          // 0..15
    const int bh = blockIdx.y;          // 0..63
    const int nb = qi + 1;

    const float* Qg = g_qkv + ((size_t)bh * NTIME + qi * 64) * NDIM;
    const float* Kg = g_qkv + QKV_SZ + (size_t)bh * NTIME * NDIM;
    const float* Vg = g_qkv + 2 * (size_t)QKV_SZ + (size_t)bh * NTIME * NDIM;

    auto load_kv = [&](int jb, int s) {
        const float* kp = Kg + (size_t)jb * 64 * 64;
        const float* vp = Vg + (size_t)jb * 64 * 64;
        const uint32_t kb = base + KS_OFF + s * 17408;
        const uint32_t vb = base + VS_OFF + s * 18432;
        #pragma unroll
        for (int i = 0; i < 8; ++i) {
            int c = tid + i * 128;
            int row = c >> 4, col = c & 15;
            cp_async16(kb + row * QS_STRIDE_B + col * 16, kp + row * 64 + col * 4);
            cp_async16(vb + row * VS_STRIDE_B + col * 16, vp + row * 64 + col * 4);
        }
    };

    // Q tile -> smem
    #pragma unroll
    for (int i = 0; i < 8; ++i) {
        int c = tid + i * 128;
        int row = c >> 4, col = c & 15;
        cp_async16(base + row * QS_STRIDE_B + col * 16, Qg + row * 64 + col * 4);
    }
    CP_COMMIT();
    load_kv(0, 0);
    CP_COMMIT();

    CP_WAIT(1);            // Q group done
    __syncthreads();

    // Q fragments (register-resident, tf32)
    const int ra = wid * 16 + grp;
    uint32_t qf[8][4];
    #pragma unroll
    for (int ks = 0; ks < 8; ++ks) {
        uint32_t a0 = base + ra * QS_STRIDE_B + (ks * 8 + qd) * 4;
        qf[ks][0] = f2tf(lds_f(a0));
        qf[ks][1] = f2tf(lds_f(a0 + 8 * QS_STRIDE_B));
        qf[ks][2] = f2tf(lds_f(a0 + 16));
        qf[ks][3] = f2tf(lds_f(a0 + 8 * QS_STRIDE_B + 16));
    }
    // Qs rows are per-warp private from here on (reused as P buffer).

    float mr0 = -1e30f, mr1 = -1e30f, lr0 = 0.f, lr1 = 0.f;
    float oacc[8][4] = {};
    const float SC = 0.18033688011112042f;   // 0.125 * log2(e)

    for (int jb = 0; jb < nb; ++jb) {
        if (jb + 1 < nb) { load_kv(jb + 1, (jb + 1) & 1); CP_COMMIT(); CP_WAIT(1); }
        else CP_WAIT(0);
        __syncthreads();

        const uint32_t kbuf = base + KS_OFF + (jb & 1) * 17408;
        const uint32_t vbuf = base + VS_OFF + (jb & 1) * 18432;

        // S = Q @ K^T
        float sv[8][4] = {};
        #pragma unroll
        for (int ks = 0; ks < 8; ++ks) {
            #pragma unroll
            for (int nt = 0; nt < 8; ++nt) {
                uint32_t addr = kbuf + (nt * 8 + grp) * QS_STRIDE_B + (ks * 8 + qd) * 4;
                uint32_t bfr[2];
                bfr[0] = f2tf(lds_f(addr));
                bfr[1] = f2tf(lds_f(addr + 16));
                mma_tf32(sv[nt], qf[ks], bfr);
            }
        }

        // scale to base-2 units + causal mask (diagonal block only)
        const bool diag = (jb == qi);
        #pragma unroll
        for (int nt = 0; nt < 8; ++nt) {
            const int c0 = nt * 8 + 2 * qd, c1 = c0 + 1;
            sv[nt][0] = (diag && c0 > ra) ? -1e30f : sv[nt][0] * SC;
            sv[nt][1] = (diag && c1 > ra) ? -1e30f : sv[nt][1] * SC;
            sv[nt][2] = (diag && c0 > ra + 8) ? -1e30f : sv[nt][2] * SC;
            sv[nt][3] = (diag && c1 > ra + 8) ? -1e30f : sv[nt][3] * SC;
        }

        // online softmax (base 2)
        float rm0 = -1e30f, rm1 = -1e30f;
        #pragma unroll
        for (int nt = 0; nt < 8; ++nt) {
            rm0 = fmaxf(rm0, fmaxf(sv[nt][0], sv[nt][1]));
            rm1 = fmaxf(rm1, fmaxf(sv[nt][2], sv[nt][3]));
        }
        rm0 = fmaxf(rm0, __shfl_xor_sync(0xffffffffu, rm0, 1));
        rm0 = fmaxf(rm0, __shfl_xor_sync(0xffffffffu, rm0, 2));
        rm1 = fmaxf(rm1, __shfl_xor_sync(0xffffffffu, rm1, 1));
        rm1 = fmaxf(rm1, __shfl_xor_sync(0xffffffffu, rm1, 2));

        const float mn0 = fmaxf(mr0, rm0), mn1 = fmaxf(mr1, rm1);
        const float a0 = exp2p(mr0 - mn0), a1 = exp2p(mr1 - mn1);

        float rs0 = 0.f, rs1 = 0.f;
        #pragma unroll
        for (int nt = 0; nt < 8; ++nt) {
            sv[nt][0] = exp2p(sv[nt][0] - mn0);
            sv[nt][1] = exp2p(sv[nt][1] - mn0);
            sv[nt][2] = exp2p(sv[nt][2] - mn1);
            sv[nt][3] = exp2p(sv[nt][3] - mn1);
            rs0 += sv[nt][0] + sv[nt][1];
            rs1 += sv[nt][2] + sv[nt][3];
        }
        rs0 += __shfl_xor_sync(0xffffffffu, rs0, 1);
        rs0 += __shfl_xor_sync(0xffffffffu, rs0, 2);
        rs1 += __shfl_xor_sync(0xffffffffu, rs1, 1);
        rs1 += __shfl_xor_sync(0xffffffffu, rs1, 2);

        lr0 = lr0 * a0 + rs0;  lr1 = lr1 * a1 + rs1;
        mr0 = mn0;             mr1 = mn1;
        #pragma unroll
        for (int nt = 0; nt < 8; ++nt) {
            oacc[nt][0] *= a0; oacc[nt][1] *= a0;
            oacc[nt][2] *= a1; oacc[nt][3] *= a1;
        }

        // P (tf32 bits) -> per-warp-private rows of the Q buffer
        #pragma unroll
        for (int nt = 0; nt < 8; ++nt) {
            const uint32_t pa = base + ra * QS_STRIDE_B + (nt * 8 + 2 * qd) * 4;
            sts_v2u(pa,                     f2tf(sv[nt][0]), f2tf(sv[nt][1]));
            sts_v2u(pa + 8 * QS_STRIDE_B,   f2tf(sv[nt][2]), f2tf(sv[nt][3]));
        }
        __syncwarp();

        // O += P @ V
        #pragma unroll
        for (int ks = 0; ks < 8; ++ks) {
            uint32_t pf[4];
            const uint32_t pb = base + ra * QS_STRIDE_B + (ks * 8 + qd) * 4;
            pf[0] = lds_u(pb);
            pf[1] = lds_u(pb + 8 * QS_STRIDE_B);
            pf[2] = lds_u(pb + 16);
            pf[3] = lds_u(pb + 8 * QS_STRIDE_B + 16);
            #pragma unroll
            for (int nt = 0; nt < 8; ++nt) {
                const uint32_t vaddr = vbuf + (ks * 8 + qd) * VS_STRIDE_B + (nt * 8 + grp) * 4;
                uint32_t bfr[2];
                bfr[0] = f2tf(lds_f(vaddr));
                bfr[1] = f2tf(lds_f(vaddr + 4 * VS_STRIDE_B));
                mma_tf32(oacc[nt], pf, bfr);
            }
        }
        __syncthreads();   // protect K/V buffers before next prefetch overwrites
    }

    // epilogue: write [B,T,C]
    const float il0 = 1.f / lr0, il1 = 1.f / lr1;
    const int b = bh >> 4, h = bh & 15;
    const int t0 = qi * 64 + ra;
    #pragma unroll
    for (int nt = 0; nt < 8; ++nt) {
        const int d = nt * 8 + 2 * qd;
        float2 v0 = make_float2(oacc[nt][0] * il0, oacc[nt][1] * il0);
        float2 v1 = make_float2(oacc[nt][2] * il1, oacc[nt][3] * il1);
        *reinterpret_cast<float2*>(g_shr + (size_t)(b * NTIME + t0) * NCH + h * 64 + d) = v0;
        *reinterpret_cast<float2*>(g_shr + (size_t)(b * NTIME + t0 + 8) * NCH + h * 64 + d) = v1;
    }
    (void)gout;
}

// ===========================================================================
// Host launch
// ===========================================================================
extern "C" void kernel_launch(void* const* d_in, const int* in_sizes, int n_in,
                              void* d_out, int out_size) {
    const float* x     = (const float*)d_in[0];
    // d_in[1] = mask (exact causal -1e9 mask; reproduced in-kernel, unused)
    const float* W_in  = (const float*)d_in[2];
    const float* b_in  = (const float*)d_in[3];
    const float* W_out = (const float*)d_in[4];
    const float* b_out = (const float*)d_in[5];
    float* out = (float*)d_out;

    void *p_qkv = nullptr, *p_shr = nullptr;
    cudaGetSymbolAddress(&p_qkv, g_qkv);
    cudaGetSymbolAddress(&p_shr, g_shr);
    float* qkv = (float*)p_qkv;
    float* shr = (float*)p_shr;

    cudaFuncSetAttribute(gemm_mma, cudaFuncAttributeMaxDynamicSharedMemorySize, GEMM_SMEM);
    cudaFuncSetAttribute(attn_mma, cudaFuncAttributeMaxDynamicSharedMemorySize, ATT_SMEM);

    // 1) W_in^T into shared region
    transpose_k<<<dim3(96, 32), dim3(32, 8)>>>(W_in, shr, 1024, 3072);

    // 2) QKV projection (scatter to head layout)
    gemm_mma<<<dim3(24, 32), 256, GEMM_SMEM>>>(x, shr, b_in, nullptr, 1024, 1);

    // 3) Tensor-core flash attention: qkv -> shr
    attn_mma<<<dim3(16, 64), 128, ATT_SMEM>>>(shr);

    // 4) W_out^T into Q region (Q dead after attention)
    transpose_k<<<dim3(32, 32), dim3(32, 8)>>>(W_out, qkv, 1024, 1024);

    // 5) Output projection
    gemm_mma<<<dim3(8, 32), 256, GEMM_SMEM>>>(shr, qkv, b_out, out, 1024, 0);
}

// round 6
// speedup vs baseline: 3.4905x; 1.1071x over previous
#include <cuda_runtime.h>
#include <cstdint>

// Problem: B=4, T=1024, C=1024, H=16, D=64; M = B*T = 4096
// inputs: x[4,1024,1024], mask (ignored; exact causal mask reproduced in-kernel),
//         W_in[1024,3072], b_in[3072], W_out[1024,1024], b_out[1024]
// output: [4,1024,1024] fp32

#define NBATCH 4
#define NTIME 1024
#define NCH   1024
#define NHEAD 16
#define NDIM  64

// 64 MB scratch with lifetime overlays (known-good footprint):
//   g_qkv [48MB]: q|k|v head layout; Q region reused for W_out^T after attention.
//   g_shr [16MB]: W_in^T (dead after gemm_qkv), then attention output [B,T,C].
// All scratch tensors are stored PRE-ROUNDED to tf32 (bit-identical to rounding
// at fragment-load time, which is what previous rounds did).
__device__ float g_qkv[3 * NBATCH * NHEAD * NTIME * NDIM];  // 48 MB
__device__ float g_shr[NBATCH * NTIME * NCH];               // 16 MB

#define QKV_SZ (NBATCH * NHEAD * NTIME * NDIM)   // 4M floats

// ===========================================================================
// PTX helpers (base sm_100 target — NO 'a'-suffix features)
// ===========================================================================
__device__ __forceinline__ uint32_t smem_u32(const void* p) {
    uint32_t a;
    asm("{ .reg .u64 t; cvta.to.shared.u64 t, %1; cvt.u32.u64 %0, t; }" : "=r"(a) : "l"(p));
    return a;
}

__device__ __forceinline__ void cp_async16(uint32_t dst, const void* src) {
    asm volatile("cp.async.cg.shared.global [%0], [%1], 16;" :: "r"(dst), "l"(src));
}
#define CP_COMMIT() asm volatile("cp.async.commit_group;" ::: "memory")
#define CP_WAIT(n)  asm volatile("cp.async.wait_group %0;" :: "n"(n) : "memory")

__device__ __forceinline__ uint32_t f2tf(float f) {
    uint32_t r;
    asm("cvt.rna.tf32.f32 %0, %1;" : "=r"(r) : "f"(f));
    return r;
}
__device__ __forceinline__ float f2tff(float f) {
    return __uint_as_float(f2tf(f));
}

__device__ __forceinline__ float lds_f(uint32_t a) {
    float v;
    asm volatile("ld.shared.f32 %0, [%1];" : "=f"(v) : "r"(a));
    return v;
}
__device__ __forceinline__ uint32_t lds_u(uint32_t a) {
    uint32_t v;
    asm volatile("ld.shared.b32 %0, [%1];" : "=r"(v) : "r"(a));
    return v;
}
__device__ __forceinline__ void sts_v2u(uint32_t a, uint32_t x, uint32_t y) {
    asm volatile("st.shared.v2.b32 [%0], {%1, %2};" :: "r"(a), "r"(x), "r"(y) : "memory");
}

__device__ __forceinline__ void mma_tf32(float* d, const uint32_t* a, const uint32_t* b) {
    asm volatile(
        "mma.sync.aligned.m16n8k8.row.col.f32.tf32.tf32.f32 "
        "{%0,%1,%2,%3}, {%4,%5,%6,%7}, {%8,%9}, {%0,%1,%2,%3};"
        : "+f"(d[0]), "+f"(d[1]), "+f"(d[2]), "+f"(d[3])
        : "r"(a[0]), "r"(a[1]), "r"(a[2]), "r"(a[3]), "r"(b[0]), "r"(b[1]));
}

// Polynomial exp2 on FMA/ALU pipes (avoids MUFU throughput wall).
__device__ __forceinline__ float exp2p(float x) {
    x = fmaxf(x, -126.0f);
    float n = rintf(x);
    float f = x - n;
    float p = 0.0013333558f;
    p = fmaf(p, f, 0.0096181291f);
    p = fmaf(p, f, 0.0555041087f);
    p = fmaf(p, f, 0.2402265070f);
    p = fmaf(p, f, 0.6931471806f);
    p = fmaf(p, f, 1.0f);
    int e = (int)n;
    return __int_as_float((e + 127) << 23) * p;
}

// ===========================================================================
// tf32 mma.sync GEMM: D = A @ Bt^T (+bias)
// ACVT=1: convert A fragments from fp32 (A not pre-rounded, e.g. input x).
// ACVT=0: A is pre-rounded tf32 bits; raw loads.
// B (Bt) is ALWAYS pre-rounded (transpose kernels round).
// mode 0: out = acc + bias (fp32, final output)
// mode 1: scatter q/k/v head layout, stored PRE-ROUNDED tf32.
// ===========================================================================
#define BM 128
#define BN 128
#define BK 32
#define STAGES 3
#define TILE_BYTES (BM * BK * 4)
#define STAGE_BYTES (2 * TILE_BYTES)
#define GEMM_SMEM (STAGES * STAGE_BYTES)

__device__ __forceinline__ uint32_t sw_addr(uint32_t base, int row, int k) {
    return base + row * 128 + ((((k >> 2) ^ row) & 7) << 4) + ((k & 3) << 2);
}

template <int ACVT>
__global__ __launch_bounds__(256, 1) void gemm_mma(
    const float* __restrict__ A, const float* __restrict__ Bt,
    const float* __restrict__ bias, float* __restrict__ outp, int K, int mode)
{
    extern __shared__ char smem[];
    const uint32_t base = smem_u32(smem);
    const int tid = threadIdx.x;
    const int lane = tid & 31, wid = tid >> 5;
    const int wm = wid >> 1, wn = wid & 1;
    const int m0 = blockIdx.y * BM;
    const int n0 = blockIdx.x * BN;
    const int NK = K / BK;

    auto load_stage = [&](int kt, int s) {
        const uint32_t sA = base + s * STAGE_BYTES;
        const uint32_t sB = sA + TILE_BYTES;
        const int k0 = kt * BK;
        #pragma unroll
        for (int i = 0; i < 4; ++i) {
            int chunk = tid + i * 256;
            int row = chunk >> 3, c16 = chunk & 7;
            uint32_t off = row * 128 + (((c16 ^ row) & 7) << 4);
            cp_async16(sA + off, A  + (size_t)(m0 + row) * K + k0 + c16 * 4);
            cp_async16(sB + off, Bt + (size_t)(n0 + row) * K + k0 + c16 * 4);
        }
    };

    float acc[2][8][4] = {};

    #pragma unroll
    for (int s = 0; s < STAGES - 1; ++s) { load_stage(s, s); CP_COMMIT(); }

    for (int kt = 0; kt < NK; ++kt) {
        CP_WAIT(STAGES - 2);
        __syncthreads();

        int ktn = kt + STAGES - 1;
        if (ktn < NK) load_stage(ktn, ktn % STAGES);
        CP_COMMIT();

        const int s = kt % STAGES;
        const uint32_t sA = base + s * STAGE_BYTES;
        const uint32_t sB = sA + TILE_BYTES;

        #pragma unroll
        for (int ks = 0; ks < 4; ++ks) {
            const int kk = ks * 8;
            uint32_t af[2][4], bf[8][2];
            #pragma unroll
            for (int mt = 0; mt < 2; ++mt) {
                int r = wm * 32 + mt * 16 + (lane >> 2);
                int c = kk + (lane & 3);
                if (ACVT) {
                    af[mt][0] = f2tf(lds_f(sw_addr(sA, r,     c)));
                    af[mt][1] = f2tf(lds_f(sw_addr(sA, r + 8, c)));
                    af[mt][2] = f2tf(lds_f(sw_addr(sA, r,     c + 4)));
                    af[mt][3] = f2tf(lds_f(sw_addr(sA, r + 8, c + 4)));
                } else {
                    af[mt][0] = lds_u(sw_addr(sA, r,     c));
                    af[mt][1] = lds_u(sw_addr(sA, r + 8, c));
                    af[mt][2] = lds_u(sw_addr(sA, r,     c + 4));
                    af[mt][3] = lds_u(sw_addr(sA, r + 8, c + 4));
                }
            }
            #pragma unroll
            for (int nt = 0; nt < 8; ++nt) {
                int n = wn * 64 + nt * 8 + (lane >> 2);
                int c = kk + (lane & 3);
                bf[nt][0] = lds_u(sw_addr(sB, n, c));
                bf[nt][1] = lds_u(sw_addr(sB, n, c + 4));
            }
            #pragma unroll
            for (int mt = 0; mt < 2; ++mt)
                #pragma unroll
                for (int nt = 0; nt < 8; ++nt)
                    mma_tf32(acc[mt][nt], af[mt], bf[nt]);
        }
    }

    #pragma unroll
    for (int mt = 0; mt < 2; ++mt) {
        const int r0 = m0 + wm * 32 + mt * 16 + (lane >> 2);
        #pragma unroll
        for (int nt = 0; nt < 8; ++nt) {
            const int c = n0 + wn * 64 + nt * 8 + (lane & 3) * 2;
            const float bx = __ldg(bias + c), by = __ldg(bias + c + 1);
            if (mode == 0) {
                float2 v0 = make_float2(acc[mt][nt][0] + bx, acc[mt][nt][1] + by);
                float2 v1 = make_float2(acc[mt][nt][2] + bx, acc[mt][nt][3] + by);
                *reinterpret_cast<float2*>(outp + (size_t)r0 * NCH + c) = v0;
                *reinterpret_cast<float2*>(outp + (size_t)(r0 + 8) * NCH + c) = v1;
            } else {
                const int which = n0 >> 10;
                float* dst = g_qkv + (size_t)which * QKV_SZ;
                const int cc = c & 1023;
                const int h = cc >> 6, d = cc & 63;
                {
                    int bb = r0 >> 10, t = r0 & 1023;
                    float2 v = make_float2(f2tff(acc[mt][nt][0] + bx), f2tff(acc[mt][nt][1] + by));
                    *reinterpret_cast<float2*>(dst + ((size_t)((bb * NHEAD + h) * NTIME) + t) * NDIM + d) = v;
                }
                {
                    int r1 = r0 + 8;
                    int bb = r1 >> 10, t = r1 & 1023;
                    float2 v = make_float2(f2tff(acc[mt][nt][2] + bx), f2tff(acc[mt][nt][3] + by));
                    *reinterpret_cast<float2*>(dst + ((size_t)((bb * NHEAD + h) * NTIME) + t) * NDIM + d) = v;
                }
            }
        }
    }
}

// ===========================================================================
// 32x32 tiled transpose + tf32 pre-round: dst = round_tf32(src^T)
// ===========================================================================
__global__ __launch_bounds__(256) void transpose_k(const float* __restrict__ src,
                                                   float* __restrict__ dst,
                                                   int R, int C) {
    __shared__ float t[32][33];
    const int bx = blockIdx.x * 32, by = blockIdx.y * 32;
    const int tx = threadIdx.x, ty = threadIdx.y;
    #pragma unroll
    for (int i = 0; i < 32; i += 8)
        t[ty + i][tx] = src[(size_t)(by + ty + i) * C + bx + tx];
    __syncthreads();
    #pragma unroll
    for (int i = 0; i < 32; i += 8)
        dst[(size_t)(bx + ty + i) * R + by + tx] = f2tff(t[tx][ty + i]);
}

// ===========================================================================
// Tensor-core flash attention (tf32 mma, poly-exp2 softmax, causal).
// Q/K/V are PRE-ROUNDED tf32 -> fragments load raw bits (no cvt).
// Output stored PRE-ROUNDED for gemm_out. Heavy query tiles launch first.
// ===========================================================================
#define QS_STRIDE_B 272                     // 68 floats
#define VS_STRIDE_B 288                     // 72 floats
#define KS_OFF 17408                        // after Qs (64*272)
#define VS_OFF (KS_OFF + 2 * 17408)         // 52224
#define ATT_SMEM (VS_OFF + 2 * 18432)       // 89088

__global__ __launch_bounds__(128, 2) void attn_mma() {
    extern __shared__ char smc[];
    const uint32_t base = smem_u32(smc);
    const int tid = threadIdx.x, lane = tid & 31, wid = tid >> 5;
    const int grp = lane >> 2, qd = lane & 3;
    const int qi = (int)gridDim.x - 1 - (int)blockIdx.x;  // heavy tiles first
    const int bh = blockIdx.y;
    const int nb = qi + 1;

    const float* Qg = g_qkv + ((size_t)bh * NTIME + qi * 64) * NDIM;
    const float* Kg = g_qkv + QKV_SZ + (size_t)bh * NTIME * NDIM;
    const float* Vg = g_qkv + 2 * (size_t)QKV_SZ + (size_t)bh * NTIME * NDIM;

    auto load_kv = [&](int jb, int s) {
        const float* kp = Kg + (size_t)jb * 64 * 64;
        const float* vp = Vg + (size_t)jb * 64 * 64;
        const uint32_t kb = base + KS_OFF + s * 17408;
        const uint32_t vb = base + VS_OFF + s * 18432;
        #pragma unroll
        for (int i = 0; i < 8; ++i) {
            int c = tid + i * 128;
            int row = c >> 4, col = c & 15;
            cp_async16(kb + row * QS_STRIDE_B + col * 16, kp + row * 64 + col * 4);
            cp_async16(vb + row * VS_STRIDE_B + col * 16, vp + row * 64 + col * 4);
        }
    };

    #pragma unroll
    for (int i = 0; i < 8; ++i) {
        int c = tid + i * 128;
        int row = c >> 4, col = c & 15;
        cp_async16(base + row * QS_STRIDE_B + col * 16, Qg + row * 64 + col * 4);
    }
    CP_COMMIT();
    load_kv(0, 0);
    CP_COMMIT();

    CP_WAIT(1);
    __syncthreads();

    const int ra = wid * 16 + grp;
    uint32_t qf[8][4];
    #pragma unroll
    for (int ks = 0; ks < 8; ++ks) {
        uint32_t a0 = base + ra * QS_STRIDE_B + (ks * 8 + qd) * 4;
        qf[ks][0] = lds_u(a0);
        qf[ks][1] = lds_u(a0 + 8 * QS_STRIDE_B);
        qf[ks][2] = lds_u(a0 + 16);
        qf[ks][3] = lds_u(a0 + 8 * QS_STRIDE_B + 16);
    }

    float mr0 = -1e30f, mr1 = -1e30f, lr0 = 0.f, lr1 = 0.f;
    float oacc[8][4] = {};
    const float SC = 0.18033688011112042f;   // 0.125 * log2(e)

    for (int jb = 0; jb < nb; ++jb) {
        if (jb + 1 < nb) { load_kv(jb + 1, (jb + 1) & 1); CP_COMMIT(); CP_WAIT(1); }
        else CP_WAIT(0);
        __syncthreads();

        const uint32_t kbuf = base + KS_OFF + (jb & 1) * 17408;
        const uint32_t vbuf = base + VS_OFF + (jb & 1) * 18432;

        // S = Q @ K^T
        float sv[8][4] = {};
        #pragma unroll
        for (int ks = 0; ks < 8; ++ks) {
            #pragma unroll
            for (int nt = 0; nt < 8; ++nt) {
                uint32_t addr = kbuf + (nt * 8 + grp) * QS_STRIDE_B + (ks * 8 + qd) * 4;
                uint32_t bfr[2];
                bfr[0] = lds_u(addr);
                bfr[1] = lds_u(addr + 16);
                mma_tf32(sv[nt], qf[ks], bfr);
            }
        }

        const bool diag = (jb == qi);
        #pragma unroll
        for (int nt = 0; nt < 8; ++nt) {
            const int c0 = nt * 8 + 2 * qd, c1 = c0 + 1;
            sv[nt][0] = (diag && c0 > ra) ? -1e30f : sv[nt][0] * SC;
            sv[nt][1] = (diag && c1 > ra) ? -1e30f : sv[nt][1] * SC;
            sv[nt][2] = (diag && c0 > ra + 8) ? -1e30f : sv[nt][2] * SC;
            sv[nt][3] = (diag && c1 > ra + 8) ? -1e30f : sv[nt][3] * SC;
        }

        float rm0 = -1e30f, rm1 = -1e30f;
        #pragma unroll
        for (int nt = 0; nt < 8; ++nt) {
            rm0 = fmaxf(rm0, fmaxf(sv[nt][0], sv[nt][1]));
            rm1 = fmaxf(rm1, fmaxf(sv[nt][2], sv[nt][3]));
        }
        rm0 = fmaxf(rm0, __shfl_xor_sync(0xffffffffu, rm0, 1));
        rm0 = fmaxf(rm0, __shfl_xor_sync(0xffffffffu, rm0, 2));
        rm1 = fmaxf(rm1, __shfl_xor_sync(0xffffffffu, rm1, 1));
        rm1 = fmaxf(rm1, __shfl_xor_sync(0xffffffffu, rm1, 2));

        const float mn0 = fmaxf(mr0, rm0), mn1 = fmaxf(mr1, rm1);
        const float a0 = exp2p(mr0 - mn0), a1 = exp2p(mr1 - mn1);

        float rs0 = 0.f, rs1 = 0.f;
        #pragma unroll
        for (int nt = 0; nt < 8; ++nt) {
            sv[nt][0] = exp2p(sv[nt][0] - mn0);
            sv[nt][1] = exp2p(sv[nt][1] - mn0);
            sv[nt][2] = exp2p(sv[nt][2] - mn1);
            sv[nt][3] = exp2p(sv[nt][3] - mn1);
            rs0 += sv[nt][0] + sv[nt][1];
            rs1 += sv[nt][2] + sv[nt][3];
        }
        rs0 += __shfl_xor_sync(0xffffffffu, rs0, 1);
        rs0 += __shfl_xor_sync(0xffffffffu, rs0, 2);
        rs1 += __shfl_xor_sync(0xffffffffu, rs1, 1);
        rs1 += __shfl_xor_sync(0xffffffffu, rs1, 2);

        lr0 = lr0 * a0 + rs0;  lr1 = lr1 * a1 + rs1;
        mr0 = mn0;             mr1 = mn1;
        #pragma unroll
        for (int nt = 0; nt < 8; ++nt) {
            oacc[nt][0] *= a0; oacc[nt][1] *= a0;
            oacc[nt][2] *= a1; oacc[nt][3] *= a1;
        }

        // P (tf32 bits) -> per-warp-private rows of the Q buffer
        #pragma unroll
        for (int nt = 0; nt < 8; ++nt) {
            const uint32_t pa = base + ra * QS_STRIDE_B + (nt * 8 + 2 * qd) * 4;
            sts_v2u(pa,                   f2tf(sv[nt][0]), f2tf(sv[nt][1]));
            sts_v2u(pa + 8 * QS_STRIDE_B, f2tf(sv[nt][2]), f2tf(sv[nt][3]));
        }
        __syncwarp();

        // O += P @ V
        #pragma unroll
        for (int ks = 0; ks < 8; ++ks) {
            uint32_t pf[4];
            const uint32_t pb = base + ra * QS_STRIDE_B + (ks * 8 + qd) * 4;
            pf[0] = lds_u(pb);
            pf[1] = lds_u(pb + 8 * QS_STRIDE_B);
            pf[2] = lds_u(pb + 16);
            pf[3] = lds_u(pb + 8 * QS_STRIDE_B + 16);
            #pragma unroll
            for (int nt = 0; nt < 8; ++nt) {
                const uint32_t vaddr = vbuf + (ks * 8 + qd) * VS_STRIDE_B + (nt * 8 + grp) * 4;
                uint32_t bfr[2];
                bfr[0] = lds_u(vaddr);
                bfr[1] = lds_u(vaddr + 4 * VS_STRIDE_B);
                mma_tf32(oacc[nt], pf, bfr);
            }
        }
        __syncthreads();
    }

    // epilogue: write [B,T,C], PRE-ROUNDED tf32 (gemm_out consumes raw)
    const float il0 = 1.f / lr0, il1 = 1.f / lr1;
    const int b = bh >> 4, h = bh & 15;
    const int t0 = qi * 64 + ra;
    #pragma unroll
    for (int nt = 0; nt < 8; ++nt) {
        const int d = nt * 8 + 2 * qd;
        float2 v0 = make_float2(f2tff(oacc[nt][0] * il0), f2tff(oacc[nt][1] * il0));
        float2 v1 = make_float2(f2tff(oacc[nt][2] * il1), f2tff(oacc[nt][3] * il1));
        *reinterpret_cast<float2*>(g_shr + (size_t)(b * NTIME + t0) * NCH + h * 64 + d) = v0;
        *reinterpret_cast<float2*>(g_shr + (size_t)(b * NTIME + t0 + 8) * NCH + h * 64 + d) = v1;
    }
}

// ===========================================================================
// Host launch
// ===========================================================================
extern "C" void kernel_launch(void* const* d_in, const int* in_sizes, int n_in,
                              void* d_out, int out_size) {
    const float* x     = (const float*)d_in[0];
    // d_in[1] = mask (exact causal -1e9 mask; reproduced in-kernel, unused)
    const float* W_in  = (const float*)d_in[2];
    const float* b_in  = (const float*)d_in[3];
    const float* W_out = (const float*)d_in[4];
    const float* b_out = (const float*)d_in[5];
    float* out = (float*)d_out;

    void *p_qkv = nullptr, *p_shr = nullptr;
    cudaGetSymbolAddress(&p_qkv, g_qkv);
    cudaGetSymbolAddress(&p_shr, g_shr);
    float* qkv = (float*)p_qkv;
    float* shr = (float*)p_shr;

    cudaFuncSetAttribute(gemm_mma<1>, cudaFuncAttributeMaxDynamicSharedMemorySize, GEMM_SMEM);
    cudaFuncSetAttribute(gemm_mma<0>, cudaFuncAttributeMaxDynamicSharedMemorySize, GEMM_SMEM);
    cudaFuncSetAttribute(attn_mma, cudaFuncAttributeMaxDynamicSharedMemorySize, ATT_SMEM);

    // 1) W_in^T (pre-rounded) into shared region
    transpose_k<<<dim3(96, 32), dim3(32, 8)>>>(W_in, shr, 1024, 3072);

    // 2) QKV projection (A = x needs cvt; scatter stores pre-rounded q/k/v)
    gemm_mma<1><<<dim3(24, 32), 256, GEMM_SMEM>>>(x, shr, b_in, nullptr, 1024, 1);

    // 3) Tensor-core flash attention: qkv -> shr (pre-rounded output)
    attn_mma<<<dim3(16, 64), 128, ATT_SMEM>>>();

    // 4) W_out^T (pre-rounded) into Q region (Q dead after attention)
    transpose_k<<<dim3(32, 32), dim3(32, 8)>>>(W_out, qkv, 1024, 1024);

    // 5) Output projection (A pre-rounded -> no cvt)
    gemm_mma<0><<<dim3(8, 32), 256, GEMM_SMEM>>>(shr, qkv, b_out, out, 1024, 0);
}

// round 7
// speedup vs baseline: 4.1760x; 1.1964x over previous
#include <cuda_runtime.h>
#include <cstdint>

// Problem: B=4, T=1024, C=1024, H=16, D=64; M = B*T = 4096
// inputs: x[4,1024,1024], mask (ignored; exact causal mask reproduced in-kernel),
//         W_in[1024,3072], b_in[3072], W_out[1024,1024], b_out[1024]
// output: [4,1024,1024] fp32

#define NBATCH 4
#define NTIME 1024
#define NCH   1024
#define NHEAD 16
#define NDIM  64

// 64 MB scratch, lifetime overlays. q,k stored [B,H,T,D]; V stored TRANSPOSED
// [B,H,D,T] (for ldmatrix-loadable PV operand). All pre-rounded tf32.
__device__ float g_qkv[3 * NBATCH * NHEAD * NTIME * NDIM];  // 48 MB
__device__ float g_shr[NBATCH * NTIME * NCH];               // 16 MB

#define QKV_SZ (NBATCH * NHEAD * NTIME * NDIM)   // 4M floats

// ===========================================================================
// PTX helpers (base sm_100 target)
// ===========================================================================
__device__ __forceinline__ uint32_t smem_u32(const void* p) {
    uint32_t a;
    asm("{ .reg .u64 t; cvta.to.shared.u64 t, %1; cvt.u32.u64 %0, t; }" : "=r"(a) : "l"(p));
    return a;
}

__device__ __forceinline__ void cp_async16(uint32_t dst, const void* src) {
    asm volatile("cp.async.cg.shared.global [%0], [%1], 16;" :: "r"(dst), "l"(src));
}
#define CP_COMMIT() asm volatile("cp.async.commit_group;" ::: "memory")
#define CP_WAIT(n)  asm volatile("cp.async.wait_group %0;" :: "n"(n) : "memory")

__device__ __forceinline__ uint32_t f2tf(float f) {
    uint32_t r;
    asm("cvt.rna.tf32.f32 %0, %1;" : "=r"(r) : "f"(f));
    return r;
}
__device__ __forceinline__ float f2tff(float f) { return __uint_as_float(f2tf(f)); }

__device__ __forceinline__ void sts_v2u(uint32_t a, uint32_t x, uint32_t y) {
    asm volatile("st.shared.v2.b32 [%0], {%1, %2};" :: "r"(a), "r"(x), "r"(y) : "memory");
}

// ldmatrix x4: 4 8x8-b16 matrices == 4 8x4-tf32 blocks. Per-thread row ptrs.
__device__ __forceinline__ void ldsm_x4(uint32_t* r, uint32_t addr) {
    asm volatile("ldmatrix.sync.aligned.m8n8.x4.shared.b16 {%0,%1,%2,%3}, [%4];"
        : "=r"(r[0]), "=r"(r[1]), "=r"(r[2]), "=r"(r[3]) : "r"(addr));
}

__device__ __forceinline__ void mma_tf32(float* d, const uint32_t* a, const uint32_t* b) {
    asm volatile(
        "mma.sync.aligned.m16n8k8.row.col.f32.tf32.tf32.f32 "
        "{%0,%1,%2,%3}, {%4,%5,%6,%7}, {%8,%9}, {%0,%1,%2,%3};"
        : "+f"(d[0]), "+f"(d[1]), "+f"(d[2]), "+f"(d[3])
        : "r"(a[0]), "r"(a[1]), "r"(a[2]), "r"(a[3]), "r"(b[0]), "r"(b[1]));
}

// Polynomial exp2 on FMA/ALU pipes (avoids MUFU throughput wall).
__device__ __forceinline__ float exp2p(float x) {
    x = fmaxf(x, -126.0f);
    float n = rintf(x);
    float f = x - n;
    float p = 0.0013333558f;
    p = fmaf(p, f, 0.0096181291f);
    p = fmaf(p, f, 0.0555041087f);
    p = fmaf(p, f, 0.2402265070f);
    p = fmaf(p, f, 0.6931471806f);
    p = fmaf(p, f, 1.0f);
    int e = (int)n;
    return __int_as_float((e + 127) << 23) * p;
}

// ===========================================================================
// tf32 mma.sync GEMM with ldmatrix fragment loads.
// ACVT=1: A needs tf32 rounding (input x). ACVT=0: A pre-rounded.
// mode 0: out = acc + bias. mode 1: scatter q/k/[v transposed], pre-rounded.
// ===========================================================================
#define BM 128
#define BN 128
#define BK 32
#define STAGES 3
#define TILE_BYTES (BM * BK * 4)
#define STAGE_BYTES (2 * TILE_BYTES)
#define GEMM_SMEM (STAGES * STAGE_BYTES)   // 98304

__device__ __forceinline__ uint32_t sw_addr(uint32_t base, int row, int k) {
    return base + row * 128 + ((((k >> 2) ^ row) & 7) << 4) + ((k & 3) << 2);
}

template <int ACVT>
__global__ __launch_bounds__(256, 2) void gemm_mma(
    const float* __restrict__ A, const float* __restrict__ Bt,
    const float* __restrict__ bias, float* __restrict__ outp, int K, int mode)
{
    extern __shared__ char smem[];
    const uint32_t base = smem_u32(smem);
    const int tid = threadIdx.x;
    const int lane = tid & 31, wid = tid >> 5;
    const int wm = wid >> 1, wn = wid & 1;
    const int m0 = blockIdx.y * BM;
    const int n0 = blockIdx.x * BN;
    const int NK = K / BK;

    // ldmatrix per-lane geometry
    const int a_row  = wm * 32 + (lane & 15);
    const int a_kadd = (lane >> 4) << 2;
    const int b_row  = wn * 64 + (lane & 7) + ((lane >> 4) << 3);
    const int b_kadd = ((lane >> 3) & 1) << 2;

    auto load_stage = [&](int kt, int s) {
        const uint32_t sA = base + s * STAGE_BYTES;
        const uint32_t sB = sA + TILE_BYTES;
        const int k0 = kt * BK;
        #pragma unroll
        for (int i = 0; i < 4; ++i) {
            int chunk = tid + i * 256;
            int row = chunk >> 3, c16 = chunk & 7;
            uint32_t off = row * 128 + (((c16 ^ row) & 7) << 4);
            cp_async16(sA + off, A  + (size_t)(m0 + row) * K + k0 + c16 * 4);
            cp_async16(sB + off, Bt + (size_t)(n0 + row) * K + k0 + c16 * 4);
        }
    };

    float acc[2][8][4] = {};

    #pragma unroll
    for (int s = 0; s < STAGES - 1; ++s) { load_stage(s, s); CP_COMMIT(); }

    for (int kt = 0; kt < NK; ++kt) {
        CP_WAIT(STAGES - 2);
        __syncthreads();

        int ktn = kt + STAGES - 1;
        if (ktn < NK) load_stage(ktn, ktn % STAGES);
        CP_COMMIT();

        const int s = kt % STAGES;
        const uint32_t sA = base + s * STAGE_BYTES;
        const uint32_t sB = sA + TILE_BYTES;

        #pragma unroll
        for (int ks = 0; ks < 4; ++ks) {
            const int kk = ks * 8;
            uint32_t af[2][4], bf[4][4];
            #pragma unroll
            for (int mt = 0; mt < 2; ++mt) {
                ldsm_x4(af[mt], sw_addr(sA, a_row + mt * 16, kk + a_kadd));
                if (ACVT) {
                    #pragma unroll
                    for (int i = 0; i < 4; ++i)
                        af[mt][i] = f2tf(__uint_as_float(af[mt][i]));
                }
            }
            #pragma unroll
            for (int p = 0; p < 4; ++p)
                ldsm_x4(bf[p], sw_addr(sB, b_row + p * 16, kk + b_kadd));
            #pragma unroll
            for (int mt = 0; mt < 2; ++mt)
                #pragma unroll
                for (int nt = 0; nt < 8; ++nt)
                    mma_tf32(acc[mt][nt], af[mt], &bf[nt >> 1][(nt & 1) * 2]);
        }
    }

    #pragma unroll
    for (int mt = 0; mt < 2; ++mt) {
        const int r0 = m0 + wm * 32 + mt * 16 + (lane >> 2);
        #pragma unroll
        for (int nt = 0; nt < 8; ++nt) {
            const int c = n0 + wn * 64 + nt * 8 + (lane & 3) * 2;
            const float bx = __ldg(bias + c), by = __ldg(bias + c + 1);
            if (mode == 0) {
                float2 v0 = make_float2(acc[mt][nt][0] + bx, acc[mt][nt][1] + by);
                float2 v1 = make_float2(acc[mt][nt][2] + bx, acc[mt][nt][3] + by);
                *reinterpret_cast<float2*>(outp + (size_t)r0 * NCH + c) = v0;
                *reinterpret_cast<float2*>(outp + (size_t)(r0 + 8) * NCH + c) = v1;
            } else {
                const int which = n0 >> 10;
                const int cc = c & 1023;
                const int h = cc >> 6, d = cc & 63;
                if (which < 2) {
                    float* dst = g_qkv + (size_t)which * QKV_SZ;
                    {
                        int bb = r0 >> 10, t = r0 & 1023;
                        float2 v = make_float2(f2tff(acc[mt][nt][0] + bx), f2tff(acc[mt][nt][1] + by));
                        *reinterpret_cast<float2*>(dst + ((size_t)((bb * NHEAD + h) * NTIME) + t) * NDIM + d) = v;
                    }
                    {
                        int r1 = r0 + 8;
                        int bb = r1 >> 10, t = r1 & 1023;
                        float2 v = make_float2(f2tff(acc[mt][nt][2] + bx), f2tff(acc[mt][nt][3] + by));
                        *reinterpret_cast<float2*>(dst + ((size_t)((bb * NHEAD + h) * NTIME) + t) * NDIM + d) = v;
                    }
                } else {
                    // V: transposed store [B,H,D,T]
                    float* dst = g_qkv + 2 * (size_t)QKV_SZ;
                    {
                        int bb = r0 >> 10, t = r0 & 1023;
                        size_t bse = ((size_t)(bb * NHEAD + h) * NDIM + d) * NTIME + t;
                        dst[bse]         = f2tff(acc[mt][nt][0] + bx);
                        dst[bse + NTIME] = f2tff(acc[mt][nt][1] + by);
                    }
                    {
                        int r1 = r0 + 8;
                        int bb = r1 >> 10, t = r1 & 1023;
                        size_t bse = ((size_t)(bb * NHEAD + h) * NDIM + d) * NTIME + t;
                        dst[bse]         = f2tff(acc[mt][nt][2] + bx);
                        dst[bse + NTIME] = f2tff(acc[mt][nt][3] + by);
                    }
                }
            }
        }
    }
}

// ===========================================================================
// 32x32 tiled transpose + tf32 pre-round
// ===========================================================================
__global__ __launch_bounds__(256) void transpose_k(const float* __restrict__ src,
                                                   float* __restrict__ dst,
                                                   int R, int C) {
    __shared__ float t[32][33];
    const int bx = blockIdx.x * 32, by = blockIdx.y * 32;
    const int tx = threadIdx.x, ty = threadIdx.y;
    #pragma unroll
    for (int i = 0; i < 32; i += 8)
        t[ty + i][tx] = src[(size_t)(by + ty + i) * C + bx + tx];
    __syncthreads();
    #pragma unroll
    for (int i = 0; i < 32; i += 8)
        dst[(size_t)(bx + ty + i) * R + by + tx] = f2tff(t[tx][ty + i]);
}

// ===========================================================================
// Tensor-core flash attention: ldmatrix fragments everywhere.
// Q/K rows = tokens; V smem rows = d (global V is [B,H,D,T]).
// All tiles stride 272 B (68 floats): every 8-row LDSM phase is conflict-free.
// ===========================================================================
#define TSTR 272                            // tile row stride bytes
#define KS_OFF 17408                        // after Q/P (64*272)
#define VS_OFF (KS_OFF + 2 * 17408)         // 52224
#define ATT_SMEM (VS_OFF + 2 * 17408)       // 87040

__global__ __launch_bounds__(128, 2) void attn_mma() {
    extern __shared__ char smc[];
    const uint32_t base = smem_u32(smc);
    const int tid = threadIdx.x, lane = tid & 31, wid = tid >> 5;
    const int grp = lane >> 2, qd = lane & 3;
    const int qi = (int)gridDim.x - 1 - (int)blockIdx.x;  // heavy tiles first
    const int bh = blockIdx.y;
    const int nb = qi + 1;

    // ldmatrix lane geometry
    const int a_row  = wid * 16 + (lane & 15);        // A-style rows (Q, P)
    const int a_kadd = (lane >> 4) << 2;
    const int b_row  = (lane & 7) + ((lane >> 4) << 3);  // B-style rows (K, V)
    const int b_kadd = ((lane >> 3) & 1) << 2;

    const float* Qg = g_qkv + ((size_t)bh * NTIME + qi * 64) * NDIM;
    const float* Kg = g_qkv + QKV_SZ + (size_t)bh * NTIME * NDIM;
    const float* Vg = g_qkv + 2 * (size_t)QKV_SZ + (size_t)bh * NDIM * NTIME; // [D,T]

    auto load_kv = [&](int jb, int s) {
        const float* kp = Kg + (size_t)jb * 64 * 64;      // 64 tokens x 64 d
        const float* vp = Vg + (size_t)jb * 64;           // 64 d rows x 64 t cols
        const uint32_t kb = base + KS_OFF + s * 17408;
        const uint32_t vb = base + VS_OFF + s * 17408;
        #pragma unroll
        for (int i = 0; i < 8; ++i) {
            int c = tid + i * 128;
            int row = c >> 4, col = c & 15;
            cp_async16(kb + row * TSTR + col * 16, kp + row * 64 + col * 4);
            cp_async16(vb + row * TSTR + col * 16, vp + (size_t)row * NTIME + col * 4);
        }
    };

    #pragma unroll
    for (int i = 0; i < 8; ++i) {
        int c = tid + i * 128;
        int row = c >> 4, col = c & 15;
        cp_async16(base + row * TSTR + col * 16, Qg + row * 64 + col * 4);
    }
    CP_COMMIT();
    load_kv(0, 0);
    CP_COMMIT();

    CP_WAIT(1);
    __syncthreads();

    // Q fragments via ldmatrix (pre-rounded tf32 bits)
    uint32_t qf[8][4];
    #pragma unroll
    for (int ks = 0; ks < 8; ++ks)
        ldsm_x4(qf[ks], base + a_row * TSTR + (ks * 8 + a_kadd) * 4);

    const int ra = wid * 16 + grp;
    float mr0 = -1e30f, mr1 = -1e30f, lr0 = 0.f, lr1 = 0.f;
    float oacc[8][4] = {};
    const float SC = 0.18033688011112042f;   // 0.125 * log2(e)

    for (int jb = 0; jb < nb; ++jb) {
        if (jb + 1 < nb) { load_kv(jb + 1, (jb + 1) & 1); CP_COMMIT(); CP_WAIT(1); }
        else CP_WAIT(0);
        __syncthreads();

        const uint32_t kbuf = base + KS_OFF + (jb & 1) * 17408;
        const uint32_t vbuf = base + VS_OFF + (jb & 1) * 17408;

        // S = Q @ K^T
        float sv[8][4] = {};
        #pragma unroll
        for (int ks = 0; ks < 8; ++ks) {
            uint32_t bf[4][4];
            #pragma unroll
            for (int p = 0; p < 4; ++p)
                ldsm_x4(bf[p], kbuf + (b_row + p * 16) * TSTR + (ks * 8 + b_kadd) * 4);
            #pragma unroll
            for (int nt = 0; nt < 8; ++nt)
                mma_tf32(sv[nt], qf[ks], &bf[nt >> 1][(nt & 1) * 2]);
        }

        const bool diag = (jb == qi);
        #pragma unroll
        for (int nt = 0; nt < 8; ++nt) {
            const int c0 = nt * 8 + 2 * qd, c1 = c0 + 1;
            sv[nt][0] = (diag && c0 > ra) ? -1e30f : sv[nt][0] * SC;
            sv[nt][1] = (diag && c1 > ra) ? -1e30f : sv[nt][1] * SC;
            sv[nt][2] = (diag && c0 > ra + 8) ? -1e30f : sv[nt][2] * SC;
            sv[nt][3] = (diag && c1 > ra + 8) ? -1e30f : sv[nt][3] * SC;
        }

        float rm0 = -1e30f, rm1 = -1e30f;
        #pragma unroll
        for (int nt = 0; nt < 8; ++nt) {
            rm0 = fmaxf(rm0, fmaxf(sv[nt][0], sv[nt][1]));
            rm1 = fmaxf(rm1, fmaxf(sv[nt][2], sv[nt][3]));
        }
        rm0 = fmaxf(rm0, __shfl_xor_sync(0xffffffffu, rm0, 1));
        rm0 = fmaxf(rm0, __shfl_xor_sync(0xffffffffu, rm0, 2));
        rm1 = fmaxf(rm1, __shfl_xor_sync(0xffffffffu, rm1, 1));
        rm1 = fmaxf(rm1, __shfl_xor_sync(0xffffffffu, rm1, 2));

        const float mn0 = fmaxf(mr0, rm0), mn1 = fmaxf(mr1, rm1);
        const float a0 = exp2p(mr0 - mn0), a1 = exp2p(mr1 - mn1);

        float rs0 = 0.f, rs1 = 0.f;
        #pragma unroll
        for (int nt = 0; nt < 8; ++nt) {
            sv[nt][0] = exp2p(sv[nt][0] - mn0);
            sv[nt][1] = exp2p(sv[nt][1] - mn0);
            sv[nt][2] = exp2p(sv[nt][2] - mn1);
            sv[nt][3] = exp2p(sv[nt][3] - mn1);
            rs0 += sv[nt][0] + sv[nt][1];
            rs1 += sv[nt][2] + sv[nt][3];
        }
        rs0 += __shfl_xor_sync(0xffffffffu, rs0, 1);
        rs0 += __shfl_xor_sync(0xffffffffu, rs0, 2);
        rs1 += __shfl_xor_sync(0xffffffffu, rs1, 1);
        rs1 += __shfl_xor_sync(0xffffffffu, rs1, 2);

        lr0 = lr0 * a0 + rs0;  lr1 = lr1 * a1 + rs1;
        mr0 = mn0;             mr1 = mn1;
        #pragma unroll
        for (int nt = 0; nt < 8; ++nt) {
            oacc[nt][0] *= a0; oacc[nt][1] *= a0;
            oacc[nt][2] *= a1; oacc[nt][3] *= a1;
        }

        // P (tf32 bits) -> per-warp-private rows of the Q buffer
        #pragma unroll
        for (int nt = 0; nt < 8; ++nt) {
            const uint32_t pa = base + ra * TSTR + (nt * 8 + 2 * qd) * 4;
            sts_v2u(pa,            f2tf(sv[nt][0]), f2tf(sv[nt][1]));
            sts_v2u(pa + 8 * TSTR, f2tf(sv[nt][2]), f2tf(sv[nt][3]));
        }
        __syncwarp();

        // O += P @ V   (V smem rows = d; B-style ldmatrix)
        #pragma unroll
        for (int ks = 0; ks < 8; ++ks) {
            uint32_t pf[4];
            ldsm_x4(pf, base + a_row * TSTR + (ks * 8 + a_kadd) * 4);
            uint32_t bf[4][4];
            #pragma unroll
            for (int p = 0; p < 4; ++p)
                ldsm_x4(bf[p], vbuf + (b_row + p * 16) * TSTR + (ks * 8 + b_kadd) * 4);
            #pragma unroll
            for (int nt = 0; nt < 8; ++nt)
                mma_tf32(oacc[nt], pf, &bf[nt >> 1][(nt & 1) * 2]);
        }
        __syncthreads();
    }

    // epilogue: write [B,T,C], pre-rounded tf32
    const float il0 = 1.f / lr0, il1 = 1.f / lr1;
    const int b = bh >> 4, h = bh & 15;
    const int t0 = qi * 64 + ra;
    #pragma unroll
    for (int nt = 0; nt < 8; ++nt) {
        const int d = nt * 8 + 2 * qd;
        float2 v0 = make_float2(f2tff(oacc[nt][0] * il0), f2tff(oacc[nt][1] * il0));
        float2 v1 = make_float2(f2tff(oacc[nt][2] * il1), f2tff(oacc[nt][3] * il1));
        *reinterpret_cast<float2*>(g_shr + (size_t)(b * NTIME + t0) * NCH + h * 64 + d) = v0;
        *reinterpret_cast<float2*>(g_shr + (size_t)(b * NTIME + t0 + 8) * NCH + h * 64 + d) = v1;
    }
}

// ===========================================================================
// Host launch
// ===========================================================================
extern "C" void kernel_launch(void* const* d_in, const int* in_sizes, int n_in,
                              void* d_out, int out_size) {
    const float* x     = (const float*)d_in[0];
    // d_in[1] = mask (exact causal -1e9 mask; reproduced in-kernel, unused)
    const float* W_in  = (const float*)d_in[2];
    const float* b_in  = (const float*)d_in[3];
    const float* W_out = (const float*)d_in[4];
    const float* b_out = (const float*)d_in[5];
    float* out = (float*)d_out;

    void *p_qkv = nullptr, *p_shr = nullptr;
    cudaGetSymbolAddress(&p_qkv, g_qkv);
    cudaGetSymbolAddress(&p_shr, g_shr);
    float* qkv = (float*)p_qkv;
    float* shr = (float*)p_shr;

    cudaFuncSetAttribute(gemm_mma<1>, cudaFuncAttributeMaxDynamicSharedMemorySize, GEMM_SMEM);
    cudaFuncSetAttribute(gemm_mma<0>, cudaFuncAttributeMaxDynamicSharedMemorySize, GEMM_SMEM);
    cudaFuncSetAttribute(attn_mma, cudaFuncAttributeMaxDynamicSharedMemorySize, ATT_SMEM);

    // 1) W_in^T (pre-rounded) into shared region
    transpose_k<<<dim3(96, 32), dim3(32, 8)>>>(W_in, shr, 1024, 3072);

    // 2) QKV projection (A = x needs cvt; scatter stores pre-rounded q/k/vT)
    gemm_mma<1><<<dim3(24, 32), 256, GEMM_SMEM>>>(x, shr, b_in, nullptr, 1024, 1);

    // 3) Tensor-core flash attention: qkv -> shr (pre-rounded output)
    attn_mma<<<dim3(16, 64), 128, ATT_SMEM>>>();

    // 4) W_out^T (pre-rounded) into Q region (Q dead after attention)
    transpose_k<<<dim3(32, 32), dim3(32, 8)>>>(W_out, qkv, 1024, 1024);

    // 5) Output projection (A pre-rounded -> no cvt)
    gemm_mma<0><<<dim3(8, 32), 256, GEMM_SMEM>>>(shr, qkv, b_out, out, 1024, 0);
}